// round 9
// baseline (speedup 1.0000x reference)
#include <cuda_runtime.h>
#include <math.h>

#define DIMN 2048
#define NH 16
#define HD 128
#define MEMN 128
#define SEQN 2048
#define BATCH 4
#define HID 5632
#define NCHUNK (SEQN / MEMN)     // 16
#define RROWS (BATCH * MEMN)     // 512 rows per step
#define TOTAL (2 * MEMN)         // 256
#define EPS 1e-5f

// ---------------- scratch (__device__ globals; no allocation) ----------------
__device__ float g_om [RROWS * DIMN];
__device__ float g_sx [RROWS * DIMN];
__device__ float g_om2[RROWS * DIMN];
__device__ float g_h  [RROWS * DIMN];   // reused for FFN output f
__device__ float g_g1 [RROWS * HID];
__device__ float g_g3 [RROWS * HID];
__device__ float g_om4[RROWS * DIMN];
__device__ float g_mk [RROWS * DIMN];
__device__ float g_mv [RROWS * DIMN];
__device__ float g_xq [RROWS * DIMN];
__device__ float g_xk [RROWS * DIMN];
__device__ float g_xv [RROWS * DIMN];
__device__ float g_q  [BATCH * NH * MEMN  * HD];   // roped queries (x part only)
__device__ float g_k  [BATCH * NH * TOTAL * HD];
__device__ float g_v  [BATCH * NH * TOTAL * HD];
__device__ float g_s  [BATCH * NH * MEMN * TOTAL]; // scores / probs
__device__ float g_y  [BATCH * SEQN * DIMN];       // per-chunk outputs == om chain

// pre-split + pre-swizzled weights (hi/lo interleaved, GEMM B-tile layout)
__device__ unsigned g_p_wq [DIMN * DIMN * 2];
__device__ unsigned g_p_wk [DIMN * DIMN * 2];
__device__ unsigned g_p_wv [DIMN * DIMN * 2];
__device__ unsigned g_p_wo [DIMN * DIMN * 2];
__device__ unsigned g_p_wkm[DIMN * DIMN * 2];
__device__ unsigned g_p_wvm[DIMN * DIMN * 2];
__device__ unsigned g_p_wm [DIMN * DIMN * 2];
__device__ unsigned g_p_w1 [DIMN * HID  * 2];
__device__ unsigned g_p_w3 [DIMN * HID  * 2];
__device__ unsigned g_p_w2 [HID  * DIMN * 2];

// ---------------- reductions ----------------
__device__ __forceinline__ float block_sum256(float v) {
    __shared__ float sh[8];
    #pragma unroll
    for (int o = 16; o > 0; o >>= 1) v += __shfl_xor_sync(0xffffffffu, v, o);
    if ((threadIdx.x & 31) == 0) sh[threadIdx.x >> 5] = v;
    __syncthreads();
    float t = 0.f;
    if (threadIdx.x < 32) {
        t = (threadIdx.x < 8) ? sh[threadIdx.x] : 0.f;
        #pragma unroll
        for (int o = 4; o > 0; o >>= 1) t += __shfl_xor_sync(0xffffffffu, t, o);
        if (threadIdx.x == 0) sh[0] = t;
    }
    __syncthreads();
    float r = sh[0];
    __syncthreads();
    return r;
}

__device__ __forceinline__ float block_max256(float v) {
    __shared__ float sh[8];
    #pragma unroll
    for (int o = 16; o > 0; o >>= 1) v = fmaxf(v, __shfl_xor_sync(0xffffffffu, v, o));
    if ((threadIdx.x & 31) == 0) sh[threadIdx.x >> 5] = v;
    __syncthreads();
    float t = -3.4e38f;
    if (threadIdx.x < 32) {
        t = (threadIdx.x < 8) ? sh[threadIdx.x] : -3.4e38f;
        #pragma unroll
        for (int o = 4; o > 0; o >>= 1) t = fmaxf(t, __shfl_xor_sync(0xffffffffu, t, o));
        if (threadIdx.x == 0) sh[0] = t;
    }
    __syncthreads();
    float r = sh[0];
    __syncthreads();
    return r;
}

// ---------------- tf32 helpers ----------------
__device__ __forceinline__ unsigned f2tf32(float f) {
    unsigned u;
    asm("cvt.rna.tf32.f32 %0, %1;" : "=r"(u) : "f"(f));
    return u;
}

__device__ __forceinline__ void split_tf32(float f, unsigned& hi, unsigned& lo) {
    hi = f2tf32(f);
    lo = f2tf32(f - __uint_as_float(hi));
}

__device__ __forceinline__ void mma_tf32(float c[4], const unsigned a[4], const unsigned b[2]) {
    asm volatile(
        "mma.sync.aligned.m16n8k8.row.col.f32.tf32.tf32.f32 "
        "{%0,%1,%2,%3}, {%4,%5,%6,%7}, {%8,%9}, {%0,%1,%2,%3};"
        : "+f"(c[0]), "+f"(c[1]), "+f"(c[2]), "+f"(c[3])
        : "r"(a[0]), "r"(a[1]), "r"(a[2]), "r"(a[3]), "r"(b[0]), "r"(b[1]));
}

// ---------------- weight pre-split: src[K][N] fp32 -> tiled hi/lo layout ----
// Tile (kt, nt) of 32x128: 8192 words, laid out as [kr][nc][2] with
// nc = nl ^ ((kr&3)*8) -- EXACTLY the GEMM's smem BsHL layout, so the GEMM
// copies one contiguous 32KB block per K-iter.
__global__ void __launch_bounds__(256) presplit_kernel(
    unsigned* __restrict__ dst, const float* __restrict__ src, int K, int N)
{
    int idx = blockIdx.x * 256 + threadIdx.x;   // one float4 per thread
    int total = (K * N) >> 2;
    if (idx >= total) return;
    int nrow4 = N >> 2;
    int k  = idx / nrow4;
    int nn = (idx - k * nrow4) << 2;
    float4 v = ((const float4*)src)[idx];
    int kt = k >> 5, kr = k & 31;
    int nt = nn >> 7, nl = nn & 127;
    int nc = nl ^ ((kr & 3) * 8);               // 4-group stays contiguous
    size_t base = (((size_t)kt * (N >> 7) + nt) << 13)
                + ((size_t)kr * 128 + nc) * 2;
    unsigned h0, l0, h1, l1, h2, l2, h3, l3;
    split_tf32(v.x, h0, l0);
    split_tf32(v.y, h1, l1);
    split_tf32(v.z, h2, l2);
    split_tf32(v.w, h3, l3);
    *(uint4*)&dst[base]     = make_uint4(h0, l0, h1, l1);
    *(uint4*)&dst[base + 4] = make_uint4(h2, l2, h3, l3);
}

// ---------------- 3xTF32 tensor-core GEMM, pre-split B ----------------------
// C[M,N] = A[M,K] @ B[K,N]; A fp32 (split in-kernel), Bp pre-split/swizzled.
// BM=64, BN=128, BK=32, 256 threads (8 warps, 32x32 warp tiles).
// B tile: one contiguous 32KB cp.async copy per K-iter (no cvt, no regs).
// A: register prefetch + split (unchanged from R8). MMA order unchanged
// -> rel_err bit-identical to R8. Static smem = 49152 B exactly.
#define GBM 64
#define GBN 128
#define GBK 32

__global__ void __launch_bounds__(256) gemm_tf32x3_pw(
    const float* __restrict__ A, const unsigned* __restrict__ Bp,
    float* __restrict__ C, int M, int N, int K)
{
    __shared__ unsigned AsHL[GBM][GBK][2];   // [m][k][hi/lo], k ^= (m&7)*4
    __shared__ unsigned BsHL[GBK][GBN][2];   // [k][n][hi/lo], n ^= (k&3)*8 (pre-applied)

    const int tid  = threadIdx.x;
    const int lane = tid & 31;
    const int wid  = tid >> 5;
    const int warp_m = wid & 1;
    const int warp_n = wid >> 1;
    const int row0 = blockIdx.y * GBM;
    const int col0 = blockIdx.x * GBN;
    const int ntiles = N >> 7;

    unsigned sb;
    {
        void* p = &BsHL[0][0][0];
        sb = (unsigned)__cvta_generic_to_shared(p);
    }

    float4 ra[2];    // A tile 64x32 floats: 2 float4/thread

    float acc[2][4][4];
    #pragma unroll
    for (int i = 0; i < 2; i++)
        #pragma unroll
        for (int j = 0; j < 4; j++)
            #pragma unroll
            for (int l = 0; l < 4; l++) acc[i][j][l] = 0.f;

    // prologue: A tile 0 into registers
    #pragma unroll
    for (int i = 0; i < 2; i++) {
        int idx = tid + i * 256;
        int m = idx >> 3, k4 = idx & 7;
        ra[i] = *(const float4*)&A[(size_t)(row0 + m) * K + k4 * 4];
    }

    for (int kk = 0; kk < K; kk += GBK) {
        // B tile: contiguous cp.async copy (smem free after bottom sync)
        {
            const unsigned* btile = Bp
                + (((size_t)(kk >> 5) * ntiles + (col0 >> 7)) << 13);
            #pragma unroll
            for (int i = 0; i < 8; i++) {
                unsigned d = sb + (unsigned)(tid + i * 256) * 16u;
                const unsigned* g = btile + (size_t)(tid + i * 256) * 4;
                asm volatile("cp.async.cg.shared.global [%0], [%1], 16;\n"
                             :: "r"(d), "l"(g));
            }
            asm volatile("cp.async.commit_group;\n");
        }

        // A: split + store (from registers)
        #pragma unroll
        for (int i = 0; i < 2; i++) {
            int idx = tid + i * 256;
            int m = idx >> 3, k4 = idx & 7;
            int kc = (k4 * 4) ^ ((m & 7) * 4);
            unsigned h0, l0, h1, l1, h2, l2, h3, l3;
            split_tf32(ra[i].x, h0, l0);
            split_tf32(ra[i].y, h1, l1);
            split_tf32(ra[i].z, h2, l2);
            split_tf32(ra[i].w, h3, l3);
            *(uint4*)&AsHL[m][kc][0]     = make_uint4(h0, l0, h1, l1);
            *(uint4*)&AsHL[m][kc + 2][0] = make_uint4(h2, l2, h3, l3);
        }

        // prefetch next A tile
        const bool more = (kk + GBK < K);
        if (more) {
            #pragma unroll
            for (int i = 0; i < 2; i++) {
                int idx = tid + i * 256;
                int m = idx >> 3, k4 = idx & 7;
                ra[i] = *(const float4*)&A[(size_t)(row0 + m) * K + kk + GBK + k4 * 4];
            }
        }

        asm volatile("cp.async.wait_group 0;\n" ::: "memory");
        __syncthreads();

        // ---- compute: 4 k-slices x 24 MMAs ----
        #pragma unroll
        for (int ks = 0; ks < 4; ks++) {
            int kq = ks * 8 + (lane & 3);
            int swb = (lane & 3) * 8;
            unsigned afH[2][4], afL[2][4];
            unsigned bfH[4][2], bfL[4][2];
            #pragma unroll
            for (int mf = 0; mf < 2; mf++) {
                int m  = warp_m * 32 + mf * 16 + (lane >> 2);
                int sw = (lane >> 2) * 4;
                uint2 a0 = *(const uint2*)&AsHL[m][kq ^ sw][0];
                uint2 a1 = *(const uint2*)&AsHL[m + 8][kq ^ sw][0];
                uint2 a2 = *(const uint2*)&AsHL[m][(kq + 4) ^ sw][0];
                uint2 a3 = *(const uint2*)&AsHL[m + 8][(kq + 4) ^ sw][0];
                afH[mf][0] = a0.x; afL[mf][0] = a0.y;
                afH[mf][1] = a1.x; afL[mf][1] = a1.y;
                afH[mf][2] = a2.x; afL[mf][2] = a2.y;
                afH[mf][3] = a3.x; afL[mf][3] = a3.y;
            }
            #pragma unroll
            for (int nf = 0; nf < 4; nf++) {
                int n = warp_n * 32 + nf * 8 + (lane >> 2);
                uint2 b0 = *(const uint2*)&BsHL[kq][n ^ swb][0];
                uint2 b1 = *(const uint2*)&BsHL[kq + 4][n ^ swb][0];
                bfH[nf][0] = b0.x; bfL[nf][0] = b0.y;
                bfH[nf][1] = b1.x; bfL[nf][1] = b1.y;
            }
            #pragma unroll
            for (int mf = 0; mf < 2; mf++)
                #pragma unroll
                for (int nf = 0; nf < 4; nf++) {
                    mma_tf32(acc[mf][nf], afL[mf], bfH[nf]);  // Al*Bh
                    mma_tf32(acc[mf][nf], afH[mf], bfL[nf]);  // Ah*Bl
                    mma_tf32(acc[mf][nf], afH[mf], bfH[nf]);  // Ah*Bh (largest last)
                }
        }
        __syncthreads();   // done reading smem; next iter overwrites
    }

    // epilogue
    #pragma unroll
    for (int mf = 0; mf < 2; mf++) {
        int row = row0 + warp_m * 32 + mf * 16 + (lane >> 2);
        #pragma unroll
        for (int nf = 0; nf < 4; nf++) {
            int col = col0 + warp_n * 32 + nf * 8 + 2 * (lane & 3);
            *(float2*)&C[(size_t)row * N + col] =
                make_float2(acc[mf][nf][0], acc[mf][nf][1]);
            *(float2*)&C[(size_t)(row + 8) * N + col] =
                make_float2(acc[mf][nf][2], acc[mf][nf][3]);
        }
    }
}

// ---------------- gather rows of a [B][SEQ][DIM] tensor chunk into [512][DIM]
__global__ void __launch_bounds__(256) gather_rows(
    float* __restrict__ dst, const float* __restrict__ src, int chunk)
{
    int row = blockIdx.x;                // 0..511
    int b = row >> 7, i = row & 127;
    const float4* s = (const float4*)&src[((size_t)b * SEQN + chunk * MEMN + i) * DIMN];
    float4* d = (float4*)&dst[(size_t)row * DIMN];
    #pragma unroll
    for (int t = 0; t < 2; t++) d[threadIdx.x + t * 256] = s[threadIdx.x + t * 256];
}

// ---------------- rmsnorm: out = in * rsqrt(mean(in^2)+eps) * w --------------
__global__ void __launch_bounds__(256) rmsnorm_kernel(
    float* __restrict__ out, const float* __restrict__ in, const float* __restrict__ w)
{
    int row = blockIdx.x;
    const float* xr = in + (size_t)row * DIMN;
    float vals[8];
    float ss = 0.f;
    #pragma unroll
    for (int t = 0; t < 8; t++) {
        float v = xr[threadIdx.x + t * 256];
        vals[t] = v; ss += v * v;
    }
    float tot = block_sum256(ss);
    float sc = rsqrtf(tot * (1.0f / DIMN) + EPS);
    #pragma unroll
    for (int t = 0; t < 8; t++)
        out[(size_t)row * DIMN + threadIdx.x + t * 256] =
            vals[t] * sc * w[threadIdx.x + t * 256];
}

// ---------------- out = rmsnorm(a + b) * w ----------------------------------
__global__ void __launch_bounds__(256) add_rmsnorm_kernel(
    float* __restrict__ out, const float* __restrict__ a,
    const float* __restrict__ b, const float* __restrict__ w)
{
    int row = blockIdx.x;
    const float* ar = a + (size_t)row * DIMN;
    const float* br = b + (size_t)row * DIMN;
    float vals[8];
    float ss = 0.f;
    #pragma unroll
    for (int t = 0; t < 8; t++) {
        float v = ar[threadIdx.x + t * 256] + br[threadIdx.x + t * 256];
        vals[t] = v; ss += v * v;
    }
    float tot = block_sum256(ss);
    float sc = rsqrtf(tot * (1.0f / DIMN) + EPS);
    #pragma unroll
    for (int t = 0; t < 8; t++)
        out[(size_t)row * DIMN + threadIdx.x + t * 256] =
            vals[t] * sc * w[threadIdx.x + t * 256];
}

// ---------------- g1 = silu(g1) * g3 (float4 elementwise) -------------------
__global__ void __launch_bounds__(256) silu_mul_kernel(
    float* __restrict__ a, const float* __restrict__ b)
{
    int idx = blockIdx.x * 256 + threadIdx.x;
    int n4 = RROWS * HID / 4;
    if (idx >= n4) return;
    float4 av = ((float4*)a)[idx];
    float4 bv = ((const float4*)b)[idx];
    av.x = av.x / (1.f + expf(-av.x)) * bv.x;
    av.y = av.y / (1.f + expf(-av.y)) * bv.y;
    av.z = av.z / (1.f + expf(-av.z)) * bv.z;
    av.w = av.w / (1.f + expf(-av.w)) * bv.w;
    ((float4*)a)[idx] = av;
}

// ---------------- build K,V (all 256 positions) with RoPE on K --------------
__global__ void __launch_bounds__(256) build_kv_kernel(
    const float* __restrict__ mk, const float* __restrict__ mv,
    const float* __restrict__ xk, const float* __restrict__ xv,
    const float* __restrict__ fc, const float* __restrict__ fs,
    float* __restrict__ k, float* __restrict__ v)
{
    int idx = blockIdx.x * 256 + threadIdx.x;   // B*TOTAL*NH*64 = 1048576
    if (idx >= BATCH * TOTAL * NH * (HD / 2)) return;
    int j   = idx & 63;
    int h   = (idx >> 6) & 15;
    int pos = (idx >> 10) & 255;
    int b   = idx >> 18;
    int col = h * HD + 2 * j;
    const float *sk, *sv;
    if (pos < MEMN) {
        size_t r = (size_t)(b * MEMN + pos) * DIMN + col;
        sk = mk + r; sv = mv + r;
    } else {
        size_t r = (size_t)(b * MEMN + pos - MEMN) * DIMN + col;
        sk = xk + r; sv = xv + r;
    }
    float c = fc[pos * 64 + j], s = fs[pos * 64 + j];
    float kr = sk[0], ki = sk[1];
    size_t o = ((size_t)(b * NH + h) * TOTAL + pos) * HD + 2 * j;
    k[o]     = kr * c - ki * s;
    k[o + 1] = kr * s + ki * c;
    v[o]     = sv[0];
    v[o + 1] = sv[1];
}

// ---------------- build Q (only x part, positions 128..255) with RoPE -------
__global__ void __launch_bounds__(256) build_q_kernel(
    const float* __restrict__ xq, const float* __restrict__ fc,
    const float* __restrict__ fs, float* __restrict__ q)
{
    int idx = blockIdx.x * 256 + threadIdx.x;   // B*MEM*NH*64 = 524288
    if (idx >= BATCH * MEMN * NH * (HD / 2)) return;
    int j = idx & 63;
    int h = (idx >> 6) & 15;
    int i = (idx >> 10) & 127;
    int b = idx >> 17;
    int pos = MEMN + i;
    const float* src = xq + (size_t)(b * MEMN + i) * DIMN + h * HD + 2 * j;
    float c = fc[pos * 64 + j], s = fs[pos * 64 + j];
    float r = src[0], im = src[1];
    size_t o = ((size_t)(b * NH + h) * MEMN + i) * HD + 2 * j;
    q[o]     = r * c - im * s;
    q[o + 1] = r * s + im * c;
}

// ---------------- S[bh][i][j] = scale * q[bh][i]·k[bh][j] -------------------
// grid (jt=4, it=2, bh=64), block 256
__global__ void __launch_bounds__(256) qk_kernel(
    const float* __restrict__ q, const float* __restrict__ k,
    float* __restrict__ s, float scale)
{
    __shared__ float Qs[64][64];   // [d][i]
    __shared__ float Ks[64][64];   // [d][j]
    int bh = blockIdx.z;
    int i0 = blockIdx.y * 64;
    int j0 = blockIdx.x * 64;
    int tid = threadIdx.x, tx = tid & 15, ty = tid >> 4;
    const float* qb = q + (size_t)bh * MEMN * HD;
    const float* kb = k + (size_t)bh * TOTAL * HD;
    float acc[4][4] = {};

    for (int dc = 0; dc < HD; dc += 64) {
        for (int t = tid; t < 64 * 16; t += 256) {
            int r = t >> 4;
            int c4 = (t & 15) * 4;
            float4 a = *(const float4*)&qb[(size_t)(i0 + r) * HD + dc + c4];
            Qs[c4 + 0][r] = a.x; Qs[c4 + 1][r] = a.y;
            Qs[c4 + 2][r] = a.z; Qs[c4 + 3][r] = a.w;
            float4 b = *(const float4*)&kb[(size_t)(j0 + r) * HD + dc + c4];
            Ks[c4 + 0][r] = b.x; Ks[c4 + 1][r] = b.y;
            Ks[c4 + 2][r] = b.z; Ks[c4 + 3][r] = b.w;
        }
        __syncthreads();
        #pragma unroll
        for (int d = 0; d < 64; d++) {
            float4 a = *(const float4*)&Qs[d][ty * 4];
            float4 b = *(const float4*)&Ks[d][tx * 4];
            float ar[4] = {a.x, a.y, a.z, a.w};
            float br[4] = {b.x, b.y, b.z, b.w};
            #pragma unroll
            for (int i = 0; i < 4; i++)
                #pragma unroll
                for (int j = 0; j < 4; j++)
                    acc[i][j] += ar[i] * br[j];
        }
        __syncthreads();
    }
    #pragma unroll
    for (int i = 0; i < 4; i++) {
        float4 o = make_float4(acc[i][0] * scale, acc[i][1] * scale,
                               acc[i][2] * scale, acc[i][3] * scale);
        *(float4*)&s[((size_t)bh * MEMN + i0 + ty * 4 + i) * TOTAL + j0 + tx * 4] = o;
    }
}

// ---------------- causal softmax over rows of S (query pos = MEM + i) -------
__global__ void __launch_bounds__(256) softmax_kernel(float* __restrict__ s)
{
    int bh = blockIdx.x >> 7;
    int i  = blockIdx.x & 127;
    float* row = s + ((size_t)bh * MEMN + i) * TOTAL;
    int tid = threadIdx.x;
    int limit = MEMN + i;           // valid keys j <= limit
    bool valid = (tid <= limit);
    float v = valid ? row[tid] : -3.4e38f;
    float m = block_max256(v);
    float e = valid ? expf(v - m) : 0.f;
    float sum = block_sum256(e);
    row[tid] = e / sum;
}

// ---------------- O = P@V, written straight into y chunk --------------------
// grid (it=2, bh=64), block 256: 64x128 output tile, 4x8 per thread
__global__ void __launch_bounds__(256) pv_kernel(
    const float* __restrict__ p, const float* __restrict__ v,
    float* __restrict__ y, int chunk)
{
    __shared__ float Ps[32][64];    // [j][i]
    __shared__ float Vs[32][128];   // [j][d]
    int bh = blockIdx.y;
    int i0 = blockIdx.x * 64;
    int b = bh >> 4, h = bh & 15;
    int tid = threadIdx.x, tx = tid & 15, ty = tid >> 4;
    const float* pb = p + (size_t)bh * MEMN * TOTAL;
    const float* vb = v + (size_t)bh * TOTAL * HD;
    float acc[4][8] = {};

    for (int j0 = 0; j0 < TOTAL; j0 += 32) {
        for (int t = tid; t < 64 * 8; t += 256) {
            int r = t >> 3;
            int c4 = (t & 7) * 4;
            float4 a = *(const float4*)&pb[(size_t)(i0 + r) * TOTAL + j0 + c4];
            Ps[c4 + 0][r] = a.x; Ps[c4 + 1][r] = a.y;
            Ps[c4 + 2][r] = a.z; Ps[c4 + 3][r] = a.w;
        }
        for (int t = tid; t < 32 * 32; t += 256) {
            int r = t >> 5;
            int c4 = (t & 31) * 4;
            *(float4*)&Vs[r][c4] = *(const float4*)&vb[(size_t)(j0 + r) * HD + c4];
        }
        __syncthreads();
        #pragma unroll
        for (int j = 0; j < 32; j++) {
            float4 a = *(const float4*)&Ps[j][ty * 4];
            float ar[4] = {a.x, a.y, a.z, a.w};
            float4 b0 = *(const float4*)&Vs[j][tx * 8];
            float4 b1 = *(const float4*)&Vs[j][tx * 8 + 4];
            float br[8] = {b0.x, b0.y, b0.z, b0.w, b1.x, b1.y, b1.z, b1.w};
            #pragma unroll
            for (int i = 0; i < 4; i++)
                #pragma unroll
                for (int jc = 0; jc < 8; jc++)
                    acc[i][jc] += ar[i] * br[jc];
        }
        __syncthreads();
    }
    #pragma unroll
    for (int i = 0; i < 4; i++) {
        size_t row = (size_t)b * SEQN + (size_t)chunk * MEMN + i0 + ty * 4 + i;
        float4 o0 = make_float4(acc[i][0], acc[i][1], acc[i][2], acc[i][3]);
        float4 o1 = make_float4(acc[i][4], acc[i][5], acc[i][6], acc[i][7]);
        *(float4*)&y[row * DIMN + h * HD + tx * 8]     = o0;
        *(float4*)&y[row * DIMN + h * HD + tx * 8 + 4] = o1;
    }
}

// ---------------- host orchestration ----------------------------------------
static void launch_gemm(const float* A, const unsigned* Bp, float* C,
                        int M, int N, int K)
{
    dim3 grid(N / GBN, M / GBM);
    gemm_tf32x3_pw<<<grid, 256>>>(A, Bp, C, M, N, K);
}

static void launch_presplit(unsigned* dst, const float* src, int K, int N)
{
    int total4 = (K * N) / 4;
    presplit_kernel<<<(total4 + 255) / 256, 256>>>(dst, src, K, N);
}

extern "C" void kernel_launch(void* const* d_in, const int* in_sizes, int n_in,
                              void* d_out, int out_size)
{
    (void)in_sizes; (void)n_in; (void)out_size;
    const float* x   = (const float*)d_in[0];
    const float* fc  = (const float*)d_in[1];
    const float* fs  = (const float*)d_in[2];
    const float* om0 = (const float*)d_in[3];
    const float* wq  = (const float*)d_in[4];
    const float* wk  = (const float*)d_in[5];
    const float* wv  = (const float*)d_in[6];
    const float* wo  = (const float*)d_in[7];
    /* d_in[8] = wqm: unused (mq = mk and mq rows are never queried) */
    const float* wkm = (const float*)d_in[9];
    const float* wvm = (const float*)d_in[10];
    const float* wm  = (const float*)d_in[11];
    const float* ffw = (const float*)d_in[12];
    const float* w1  = (const float*)d_in[13];
    const float* w2  = (const float*)d_in[14];
    const float* w3  = (const float*)d_in[15];
    const float* mnw = (const float*)d_in[16];
    float* out = (float*)d_out;

    float *om, *sx, *om2, *h, *g1, *g3, *om4, *mk, *mv, *xq, *xk, *xv;
    float *q, *k, *v, *s, *y;
    cudaGetSymbolAddress((void**)&om,  g_om);
    cudaGetSymbolAddress((void**)&sx,  g_sx);
    cudaGetSymbolAddress((void**)&om2, g_om2);
    cudaGetSymbolAddress((void**)&h,   g_h);
    cudaGetSymbolAddress((void**)&g1,  g_g1);
    cudaGetSymbolAddress((void**)&g3,  g_g3);
    cudaGetSymbolAddress((void**)&om4, g_om4);
    cudaGetSymbolAddress((void**)&mk,  g_mk);
    cudaGetSymbolAddress((void**)&mv,  g_mv);
    cudaGetSymbolAddress((void**)&xq,  g_xq);
    cudaGetSymbolAddress((void**)&xk,  g_xk);
    cudaGetSymbolAddress((void**)&xv,  g_xv);
    cudaGetSymbolAddress((void**)&q,   g_q);
    cudaGetSymbolAddress((void**)&k,   g_k);
    cudaGetSymbolAddress((void**)&v,   g_v);
    cudaGetSymbolAddress((void**)&s,   g_s);
    cudaGetSymbolAddress((void**)&y,   g_y);

    unsigned *pwq, *pwk, *pwv, *pwo, *pwkm, *pwvm, *pwm, *pw1, *pw2, *pw3;
    cudaGetSymbolAddress((void**)&pwq,  g_p_wq);
    cudaGetSymbolAddress((void**)&pwk,  g_p_wk);
    cudaGetSymbolAddress((void**)&pwv,  g_p_wv);
    cudaGetSymbolAddress((void**)&pwo,  g_p_wo);
    cudaGetSymbolAddress((void**)&pwkm, g_p_wkm);
    cudaGetSymbolAddress((void**)&pwvm, g_p_wvm);
    cudaGetSymbolAddress((void**)&pwm,  g_p_wm);
    cudaGetSymbolAddress((void**)&pw1,  g_p_w1);
    cudaGetSymbolAddress((void**)&pw2,  g_p_w2);
    cudaGetSymbolAddress((void**)&pw3,  g_p_w3);

    // pre-split + pre-swizzle all weights once per launch
    launch_presplit(pwq,  wq,  DIMN, DIMN);
    launch_presplit(pwk,  wk,  DIMN, DIMN);
    launch_presplit(pwv,  wv,  DIMN, DIMN);
    launch_presplit(pwo,  wo,  DIMN, DIMN);
    launch_presplit(pwkm, wkm, DIMN, DIMN);
    launch_presplit(pwvm, wvm, DIMN, DIMN);
    launch_presplit(pwm,  wm,  DIMN, DIMN);
    launch_presplit(pw1,  w1,  DIMN, HID);
    launch_presplit(pw3,  w3,  DIMN, HID);
    launch_presplit(pw2,  w2,  HID,  DIMN);

    const float scale = 0.08838834764831845f;   // 1/sqrt(128)

    for (int c = 0; c < NCHUNK; c++) {
        const float* omp;
        if (c == 0) {
            omp = om0;                           // origin_mem is contiguous [512][DIM]
        } else {
            gather_rows<<<RROWS, 256>>>(om, y, c - 1);
            omp = om;
        }
        gather_rows<<<RROWS, 256>>>(sx, x, c);

        // memory-stream FFN block
        launch_gemm(omp, pwm, om2, RROWS, DIMN, DIMN);
        rmsnorm_kernel<<<RROWS, 256>>>(h, om2, ffw);
        launch_gemm(h, pw1, g1, RROWS, HID, DIMN);
        launch_gemm(h, pw3, g3, RROWS, HID, DIMN);
        silu_mul_kernel<<<(RROWS * HID / 4 + 255) / 256, 256>>>(g1, g3);
        launch_gemm(g1, pw2, h, RROWS, DIMN, HID);         // f -> h (h dead now)
        add_rmsnorm_kernel<<<RROWS, 256>>>(om4, om2, h, mnw);

        // projections
        launch_gemm(om4, pwkm, mk, RROWS, DIMN, DIMN);
        launch_gemm(om4, pwvm, mv, RROWS, DIMN, DIMN);
        launch_gemm(sx,  pwq,  xq, RROWS, DIMN, DIMN);
        launch_gemm(sx,  pwk,  xk, RROWS, DIMN, DIMN);
        launch_gemm(sx,  pwv,  xv, RROWS, DIMN, DIMN);

        // assemble roped q/k/v
        build_kv_kernel<<<(BATCH * TOTAL * NH * 64 + 255) / 256, 256>>>(
            mk, mv, xk, xv, fc, fs, k, v);
        build_q_kernel<<<(BATCH * MEMN * NH * 64 + 255) / 256, 256>>>(xq, fc, fs, q);

        // attention (only output rows MEM..2*MEM-1 are needed)
        {
            dim3 g(4, 2, BATCH * NH);
            qk_kernel<<<g, 256>>>(q, k, s, scale);
        }
        softmax_kernel<<<BATCH * NH * MEMN, 256>>>(s);
        {
            dim3 g(2, BATCH * NH);
            pv_kernel<<<g, 256>>>(s, v, y, c);
        }
    }

    // final projection: out = y @ wo
    launch_gemm(y, pwo, out, BATCH * SEQN, DIMN, DIMN);
}

// round 10
// speedup vs baseline: 1.2163x; 1.2163x over previous
#include <cuda_runtime.h>
#include <math.h>

#define DIMN 2048
#define NH 16
#define HD 128
#define MEMN 128
#define SEQN 2048
#define BATCH 4
#define HID 5632
#define NCHUNK (SEQN / MEMN)     // 16
#define RROWS (BATCH * MEMN)     // 512 rows per step
#define TOTAL (2 * MEMN)         // 256
#define EPS 1e-5f

// ---------------- scratch (__device__ globals; no allocation) ----------------
__device__ float g_om [RROWS * DIMN];
__device__ float g_sx [RROWS * DIMN];
__device__ float g_om2[RROWS * DIMN];
__device__ float g_h  [RROWS * DIMN];   // reused for FFN output f
__device__ float g_g1 [RROWS * HID];
__device__ float g_g3 [RROWS * HID];
__device__ float g_om4[RROWS * DIMN];
__device__ float g_mk [RROWS * DIMN];
__device__ float g_mv [RROWS * DIMN];
__device__ float g_xq [RROWS * DIMN];
__device__ float g_xk [RROWS * DIMN];
__device__ float g_xv [RROWS * DIMN];
__device__ float g_q  [BATCH * NH * MEMN  * HD];   // roped queries (x part only)
__device__ float g_k  [BATCH * NH * TOTAL * HD];
__device__ float g_v  [BATCH * NH * TOTAL * HD];
__device__ float g_s  [BATCH * NH * MEMN * TOTAL]; // scores / probs
__device__ float g_y  [BATCH * SEQN * DIMN];       // per-chunk outputs == om chain

// pre-split + pre-swizzled weights (hi/lo interleaved, GEMM B-tile layout)
__device__ unsigned g_p_wq [DIMN * DIMN * 2];
__device__ unsigned g_p_wk [DIMN * DIMN * 2];
__device__ unsigned g_p_wv [DIMN * DIMN * 2];
__device__ unsigned g_p_wo [DIMN * DIMN * 2];
__device__ unsigned g_p_wkm[DIMN * DIMN * 2];
__device__ unsigned g_p_wvm[DIMN * DIMN * 2];
__device__ unsigned g_p_wm [DIMN * DIMN * 2];
__device__ unsigned g_p_w1 [DIMN * HID  * 2];
__device__ unsigned g_p_w3 [DIMN * HID  * 2];
__device__ unsigned g_p_w2 [HID  * DIMN * 2];

// ---------------- reductions ----------------
__device__ __forceinline__ float block_sum256(float v) {
    __shared__ float sh[8];
    #pragma unroll
    for (int o = 16; o > 0; o >>= 1) v += __shfl_xor_sync(0xffffffffu, v, o);
    if ((threadIdx.x & 31) == 0) sh[threadIdx.x >> 5] = v;
    __syncthreads();
    float t = 0.f;
    if (threadIdx.x < 32) {
        t = (threadIdx.x < 8) ? sh[threadIdx.x] : 0.f;
        #pragma unroll
        for (int o = 4; o > 0; o >>= 1) t += __shfl_xor_sync(0xffffffffu, t, o);
        if (threadIdx.x == 0) sh[0] = t;
    }
    __syncthreads();
    float r = sh[0];
    __syncthreads();
    return r;
}

__device__ __forceinline__ float block_max256(float v) {
    __shared__ float sh[8];
    #pragma unroll
    for (int o = 16; o > 0; o >>= 1) v = fmaxf(v, __shfl_xor_sync(0xffffffffu, v, o));
    if ((threadIdx.x & 31) == 0) sh[threadIdx.x >> 5] = v;
    __syncthreads();
    float t = -3.4e38f;
    if (threadIdx.x < 32) {
        t = (threadIdx.x < 8) ? sh[threadIdx.x] : -3.4e38f;
        #pragma unroll
        for (int o = 4; o > 0; o >>= 1) t = fmaxf(t, __shfl_xor_sync(0xffffffffu, t, o));
        if (threadIdx.x == 0) sh[0] = t;
    }
    __syncthreads();
    float r = sh[0];
    __syncthreads();
    return r;
}

// ---------------- tf32 helpers ----------------
__device__ __forceinline__ unsigned f2tf32(float f) {
    unsigned u;
    asm("cvt.rna.tf32.f32 %0, %1;" : "=r"(u) : "f"(f));
    return u;
}

__device__ __forceinline__ void split_tf32(float f, unsigned& hi, unsigned& lo) {
    hi = f2tf32(f);
    lo = f2tf32(f - __uint_as_float(hi));
}

__device__ __forceinline__ void mma_tf32(float c[4], const unsigned a[4], const unsigned b[2]) {
    asm volatile(
        "mma.sync.aligned.m16n8k8.row.col.f32.tf32.tf32.f32 "
        "{%0,%1,%2,%3}, {%4,%5,%6,%7}, {%8,%9}, {%0,%1,%2,%3};"
        : "+f"(c[0]), "+f"(c[1]), "+f"(c[2]), "+f"(c[3])
        : "r"(a[0]), "r"(a[1]), "r"(a[2]), "r"(a[3]), "r"(b[0]), "r"(b[1]));
}

// ---------------- weight pre-split: src[K][N] fp32 -> tiled hi/lo layout ----
// Tile (kt, nt) of 32x128: 8192 words, laid out as [kr][nc][2] with
// nc = nl ^ ((kr&3)*8) -- EXACTLY the GEMM's smem BsHL layout, so the GEMM
// copies one contiguous 32KB block per K-iter.
__global__ void __launch_bounds__(256) presplit_kernel(
    unsigned* __restrict__ dst, const float* __restrict__ src, int K, int N)
{
    int idx = blockIdx.x * 256 + threadIdx.x;   // one float4 per thread
    int total = (K * N) >> 2;
    if (idx >= total) return;
    int nrow4 = N >> 2;
    int k  = idx / nrow4;
    int nn = (idx - k * nrow4) << 2;
    float4 v = ((const float4*)src)[idx];
    int kt = k >> 5, kr = k & 31;
    int nt = nn >> 7, nl = nn & 127;
    int nc = nl ^ ((kr & 3) * 8);               // 4-group stays contiguous
    size_t base = (((size_t)kt * (N >> 7) + nt) << 13)
                + ((size_t)kr * 128 + nc) * 2;
    unsigned h0, l0, h1, l1, h2, l2, h3, l3;
    split_tf32(v.x, h0, l0);
    split_tf32(v.y, h1, l1);
    split_tf32(v.z, h2, l2);
    split_tf32(v.w, h3, l3);
    *(uint4*)&dst[base]     = make_uint4(h0, l0, h1, l1);
    *(uint4*)&dst[base + 4] = make_uint4(h2, l2, h3, l3);
}

// ---------------- 3xTF32 tensor-core GEMM, pre-split B, 2-stage pipeline ----
// C[M,N] = A[M,K] @ B[K,N]; A fp32 (split in-kernel), Bp pre-split/swizzled.
// BM=64, BN=128, BK=32, 256 threads (8 warps, 32x32 warp tiles).
// NEW (R10): double-buffered smem (dynamic, 96KB). cp.async for B(next) and
// LDG for A(next) issue BEFORE the 96-MMA compute block, so copy latency
// hides under compute (restores R8's hiding that R9 lost). MMA order per k
// unchanged -> rel_err bit-identical.
#define GBM 64
#define GBN 128
#define GBK 32
#define A_BUF_WORDS (GBM * GBK * 2)   // 4096 words = 16KB
#define B_BUF_WORDS (GBK * GBN * 2)   // 8192 words = 32KB
#define GEMM_SMEM ((2 * A_BUF_WORDS + 2 * B_BUF_WORDS) * 4)   // 98304 B

__global__ void __launch_bounds__(256) gemm_tf32x3_pw(
    const float* __restrict__ A, const unsigned* __restrict__ Bp,
    float* __restrict__ C, int M, int N, int K)
{
    extern __shared__ unsigned su[];
    // layout: As[0], As[1], Bs[0], Bs[1]
    typedef unsigned ABuf[GBM][GBK][2];
    typedef unsigned BBuf[GBK][GBN][2];
    ABuf* As = (ABuf*)su;                          // As[buf][m][k][hl], k ^= (m&7)*4
    BBuf* Bs = (BBuf*)(su + 2 * A_BUF_WORDS);      // Bs[buf][k][n][hl], n pre-swizzled

    const int tid  = threadIdx.x;
    const int lane = tid & 31;
    const int wid  = tid >> 5;
    const int warp_m = wid & 1;
    const int warp_n = wid >> 1;
    const int row0 = blockIdx.y * GBM;
    const int col0 = blockIdx.x * GBN;
    const int ntiles = N >> 7;

    unsigned sbB[2];
    sbB[0] = (unsigned)__cvta_generic_to_shared(&Bs[0][0][0][0]);
    sbB[1] = (unsigned)__cvta_generic_to_shared(&Bs[1][0][0][0]);

    float4 ra[2];    // A tile 64x32 floats: 2 float4/thread

    float acc[2][4][4];
    #pragma unroll
    for (int i = 0; i < 2; i++)
        #pragma unroll
        for (int j = 0; j < 4; j++)
            #pragma unroll
            for (int l = 0; l < 4; l++) acc[i][j][l] = 0.f;

    // ---- prologue: stage 0 ----
    {
        const unsigned* btile = Bp + (((size_t)0 * ntiles + (col0 >> 7)) << 13);
        #pragma unroll
        for (int i = 0; i < 8; i++) {
            unsigned d = sbB[0] + (unsigned)(tid + i * 256) * 16u;
            const unsigned* g = btile + (size_t)(tid + i * 256) * 4;
            asm volatile("cp.async.cg.shared.global [%0], [%1], 16;\n"
                         :: "r"(d), "l"(g));
        }
        asm volatile("cp.async.commit_group;\n");
    }
    #pragma unroll
    for (int i = 0; i < 2; i++) {
        int idx = tid + i * 256;
        int m = idx >> 3, k4 = idx & 7;
        ra[i] = *(const float4*)&A[(size_t)(row0 + m) * K + k4 * 4];
    }
    #pragma unroll
    for (int i = 0; i < 2; i++) {
        int idx = tid + i * 256;
        int m = idx >> 3, k4 = idx & 7;
        int kc = (k4 * 4) ^ ((m & 7) * 4);
        unsigned h0, l0, h1, l1, h2, l2, h3, l3;
        split_tf32(ra[i].x, h0, l0);
        split_tf32(ra[i].y, h1, l1);
        split_tf32(ra[i].z, h2, l2);
        split_tf32(ra[i].w, h3, l3);
        *(uint4*)&As[0][m][kc][0]     = make_uint4(h0, l0, h1, l1);
        *(uint4*)&As[0][m][kc + 2][0] = make_uint4(h2, l2, h3, l3);
    }
    asm volatile("cp.async.wait_group 0;\n" ::: "memory");
    __syncthreads();

    int buf = 0;
    for (int kk = 0; kk < K; kk += GBK) {
        const int nxt = buf ^ 1;
        const bool more = (kk + GBK < K);

        // issue next stage's copies BEFORE compute
        if (more) {
            const unsigned* btile = Bp
                + (((size_t)((kk + GBK) >> 5) * ntiles + (col0 >> 7)) << 13);
            #pragma unroll
            for (int i = 0; i < 8; i++) {
                unsigned d = sbB[nxt] + (unsigned)(tid + i * 256) * 16u;
                const unsigned* g = btile + (size_t)(tid + i * 256) * 4;
                asm volatile("cp.async.cg.shared.global [%0], [%1], 16;\n"
                             :: "r"(d), "l"(g));
            }
            asm volatile("cp.async.commit_group;\n");
            #pragma unroll
            for (int i = 0; i < 2; i++) {
                int idx = tid + i * 256;
                int m = idx >> 3, k4 = idx & 7;
                ra[i] = *(const float4*)&A[(size_t)(row0 + m) * K + kk + GBK + k4 * 4];
            }
        }

        // ---- compute on buf: 4 k-slices x 24 MMAs ----
        #pragma unroll
        for (int ks = 0; ks < 4; ks++) {
            int kq = ks * 8 + (lane & 3);
            int swb = (lane & 3) * 8;
            unsigned afH[2][4], afL[2][4];
            unsigned bfH[4][2], bfL[4][2];
            #pragma unroll
            for (int mf = 0; mf < 2; mf++) {
                int m  = warp_m * 32 + mf * 16 + (lane >> 2);
                int sw = (lane >> 2) * 4;
                uint2 a0 = *(const uint2*)&As[buf][m][kq ^ sw][0];
                uint2 a1 = *(const uint2*)&As[buf][m + 8][kq ^ sw][0];
                uint2 a2 = *(const uint2*)&As[buf][m][(kq + 4) ^ sw][0];
                uint2 a3 = *(const uint2*)&As[buf][m + 8][(kq + 4) ^ sw][0];
                afH[mf][0] = a0.x; afL[mf][0] = a0.y;
                afH[mf][1] = a1.x; afL[mf][1] = a1.y;
                afH[mf][2] = a2.x; afL[mf][2] = a2.y;
                afH[mf][3] = a3.x; afL[mf][3] = a3.y;
            }
            #pragma unroll
            for (int nf = 0; nf < 4; nf++) {
                int n = warp_n * 32 + nf * 8 + (lane >> 2);
                uint2 b0 = *(const uint2*)&Bs[buf][kq][n ^ swb][0];
                uint2 b1 = *(const uint2*)&Bs[buf][kq + 4][n ^ swb][0];
                bfH[nf][0] = b0.x; bfL[nf][0] = b0.y;
                bfH[nf][1] = b1.x; bfL[nf][1] = b1.y;
            }
            #pragma unroll
            for (int mf = 0; mf < 2; mf++)
                #pragma unroll
                for (int nf = 0; nf < 4; nf++) {
                    mma_tf32(acc[mf][nf], afL[mf], bfH[nf]);  // Al*Bh
                    mma_tf32(acc[mf][nf], afH[mf], bfL[nf]);  // Ah*Bl
                    mma_tf32(acc[mf][nf], afH[mf], bfH[nf]);  // Ah*Bh (largest last)
                }
        }

        // stage next A into the other buffer; wait for next B
        if (more) {
            #pragma unroll
            for (int i = 0; i < 2; i++) {
                int idx = tid + i * 256;
                int m = idx >> 3, k4 = idx & 7;
                int kc = (k4 * 4) ^ ((m & 7) * 4);
                unsigned h0, l0, h1, l1, h2, l2, h3, l3;
                split_tf32(ra[i].x, h0, l0);
                split_tf32(ra[i].y, h1, l1);
                split_tf32(ra[i].z, h2, l2);
                split_tf32(ra[i].w, h3, l3);
                *(uint4*)&As[nxt][m][kc][0]     = make_uint4(h0, l0, h1, l1);
                *(uint4*)&As[nxt][m][kc + 2][0] = make_uint4(h2, l2, h3, l3);
            }
            asm volatile("cp.async.wait_group 0;\n" ::: "memory");
        }
        __syncthreads();
        buf = nxt;
    }

    // epilogue
    #pragma unroll
    for (int mf = 0; mf < 2; mf++) {
        int row = row0 + warp_m * 32 + mf * 16 + (lane >> 2);
        #pragma unroll
        for (int nf = 0; nf < 4; nf++) {
            int col = col0 + warp_n * 32 + nf * 8 + 2 * (lane & 3);
            *(float2*)&C[(size_t)row * N + col] =
                make_float2(acc[mf][nf][0], acc[mf][nf][1]);
            *(float2*)&C[(size_t)(row + 8) * N + col] =
                make_float2(acc[mf][nf][2], acc[mf][nf][3]);
        }
    }
}

// ---------------- gather rows of a [B][SEQ][DIM] tensor chunk into [512][DIM]
__global__ void __launch_bounds__(256) gather_rows(
    float* __restrict__ dst, const float* __restrict__ src, int chunk)
{
    int row = blockIdx.x;                // 0..511
    int b = row >> 7, i = row & 127;
    const float4* s = (const float4*)&src[((size_t)b * SEQN + chunk * MEMN + i) * DIMN];
    float4* d = (float4*)&dst[(size_t)row * DIMN];
    #pragma unroll
    for (int t = 0; t < 2; t++) d[threadIdx.x + t * 256] = s[threadIdx.x + t * 256];
}

// ---------------- rmsnorm: out = in * rsqrt(mean(in^2)+eps) * w --------------
__global__ void __launch_bounds__(256) rmsnorm_kernel(
    float* __restrict__ out, const float* __restrict__ in, const float* __restrict__ w)
{
    int row = blockIdx.x;
    const float* xr = in + (size_t)row * DIMN;
    float vals[8];
    float ss = 0.f;
    #pragma unroll
    for (int t = 0; t < 8; t++) {
        float v = xr[threadIdx.x + t * 256];
        vals[t] = v; ss += v * v;
    }
    float tot = block_sum256(ss);
    float sc = rsqrtf(tot * (1.0f / DIMN) + EPS);
    #pragma unroll
    for (int t = 0; t < 8; t++)
        out[(size_t)row * DIMN + threadIdx.x + t * 256] =
            vals[t] * sc * w[threadIdx.x + t * 256];
}

// ---------------- out = rmsnorm(a + b) * w ----------------------------------
__global__ void __launch_bounds__(256) add_rmsnorm_kernel(
    float* __restrict__ out, const float* __restrict__ a,
    const float* __restrict__ b, const float* __restrict__ w)
{
    int row = blockIdx.x;
    const float* ar = a + (size_t)row * DIMN;
    const float* br = b + (size_t)row * DIMN;
    float vals[8];
    float ss = 0.f;
    #pragma unroll
    for (int t = 0; t < 8; t++) {
        float v = ar[threadIdx.x + t * 256] + br[threadIdx.x + t * 256];
        vals[t] = v; ss += v * v;
    }
    float tot = block_sum256(ss);
    float sc = rsqrtf(tot * (1.0f / DIMN) + EPS);
    #pragma unroll
    for (int t = 0; t < 8; t++)
        out[(size_t)row * DIMN + threadIdx.x + t * 256] =
            vals[t] * sc * w[threadIdx.x + t * 256];
}

// ---------------- g1 = silu(g1) * g3 (float4 elementwise) -------------------
__global__ void __launch_bounds__(256) silu_mul_kernel(
    float* __restrict__ a, const float* __restrict__ b)
{
    int idx = blockIdx.x * 256 + threadIdx.x;
    int n4 = RROWS * HID / 4;
    if (idx >= n4) return;
    float4 av = ((float4*)a)[idx];
    float4 bv = ((const float4*)b)[idx];
    av.x = av.x / (1.f + expf(-av.x)) * bv.x;
    av.y = av.y / (1.f + expf(-av.y)) * bv.y;
    av.z = av.z / (1.f + expf(-av.z)) * bv.z;
    av.w = av.w / (1.f + expf(-av.w)) * bv.w;
    ((float4*)a)[idx] = av;
}

// ---------------- build K,V (all 256 positions) with RoPE on K --------------
__global__ void __launch_bounds__(256) build_kv_kernel(
    const float* __restrict__ mk, const float* __restrict__ mv,
    const float* __restrict__ xk, const float* __restrict__ xv,
    const float* __restrict__ fc, const float* __restrict__ fs,
    float* __restrict__ k, float* __restrict__ v)
{
    int idx = blockIdx.x * 256 + threadIdx.x;   // B*TOTAL*NH*64 = 1048576
    if (idx >= BATCH * TOTAL * NH * (HD / 2)) return;
    int j   = idx & 63;
    int h   = (idx >> 6) & 15;
    int pos = (idx >> 10) & 255;
    int b   = idx >> 18;
    int col = h * HD + 2 * j;
    const float *sk, *sv;
    if (pos < MEMN) {
        size_t r = (size_t)(b * MEMN + pos) * DIMN + col;
        sk = mk + r; sv = mv + r;
    } else {
        size_t r = (size_t)(b * MEMN + pos - MEMN) * DIMN + col;
        sk = xk + r; sv = xv + r;
    }
    float c = fc[pos * 64 + j], s = fs[pos * 64 + j];
    float kr = sk[0], ki = sk[1];
    size_t o = ((size_t)(b * NH + h) * TOTAL + pos) * HD + 2 * j;
    k[o]     = kr * c - ki * s;
    k[o + 1] = kr * s + ki * c;
    v[o]     = sv[0];
    v[o + 1] = sv[1];
}

// ---------------- build Q (only x part, positions 128..255) with RoPE -------
__global__ void __launch_bounds__(256) build_q_kernel(
    const float* __restrict__ xq, const float* __restrict__ fc,
    const float* __restrict__ fs, float* __restrict__ q)
{
    int idx = blockIdx.x * 256 + threadIdx.x;   // B*MEM*NH*64 = 524288
    if (idx >= BATCH * MEMN * NH * (HD / 2)) return;
    int j = idx & 63;
    int h = (idx >> 6) & 15;
    int i = (idx >> 10) & 127;
    int b = idx >> 17;
    int pos = MEMN + i;
    const float* src = xq + (size_t)(b * MEMN + i) * DIMN + h * HD + 2 * j;
    float c = fc[pos * 64 + j], s = fs[pos * 64 + j];
    float r = src[0], im = src[1];
    size_t o = ((size_t)(b * NH + h) * MEMN + i) * HD + 2 * j;
    q[o]     = r * c - im * s;
    q[o + 1] = r * s + im * c;
}

// ---------------- S[bh][i][j] = scale * q[bh][i]·k[bh][j] -------------------
// grid (jt=4, it=2, bh=64), block 256
__global__ void __launch_bounds__(256) qk_kernel(
    const float* __restrict__ q, const float* __restrict__ k,
    float* __restrict__ s, float scale)
{
    __shared__ float Qs[64][64];   // [d][i]
    __shared__ float Ks[64][64];   // [d][j]
    int bh = blockIdx.z;
    int i0 = blockIdx.y * 64;
    int j0 = blockIdx.x * 64;
    int tid = threadIdx.x, tx = tid & 15, ty = tid >> 4;
    const float* qb = q + (size_t)bh * MEMN * HD;
    const float* kb = k + (size_t)bh * TOTAL * HD;
    float acc[4][4] = {};

    for (int dc = 0; dc < HD; dc += 64) {
        for (int t = tid; t < 64 * 16; t += 256) {
            int r = t >> 4;
            int c4 = (t & 15) * 4;
            float4 a = *(const float4*)&qb[(size_t)(i0 + r) * HD + dc + c4];
            Qs[c4 + 0][r] = a.x; Qs[c4 + 1][r] = a.y;
            Qs[c4 + 2][r] = a.z; Qs[c4 + 3][r] = a.w;
            float4 b = *(const float4*)&kb[(size_t)(j0 + r) * HD + dc + c4];
            Ks[c4 + 0][r] = b.x; Ks[c4 + 1][r] = b.y;
            Ks[c4 + 2][r] = b.z; Ks[c4 + 3][r] = b.w;
        }
        __syncthreads();
        #pragma unroll
        for (int d = 0; d < 64; d++) {
            float4 a = *(const float4*)&Qs[d][ty * 4];
            float4 b = *(const float4*)&Ks[d][tx * 4];
            float ar[4] = {a.x, a.y, a.z, a.w};
            float br[4] = {b.x, b.y, b.z, b.w};
            #pragma unroll
            for (int i = 0; i < 4; i++)
                #pragma unroll
                for (int j = 0; j < 4; j++)
                    acc[i][j] += ar[i] * br[j];
        }
        __syncthreads();
    }
    #pragma unroll
    for (int i = 0; i < 4; i++) {
        float4 o = make_float4(acc[i][0] * scale, acc[i][1] * scale,
                               acc[i][2] * scale, acc[i][3] * scale);
        *(float4*)&s[((size_t)bh * MEMN + i0 + ty * 4 + i) * TOTAL + j0 + tx * 4] = o;
    }
}

// ---------------- causal softmax over rows of S (query pos = MEM + i) -------
__global__ void __launch_bounds__(256) softmax_kernel(float* __restrict__ s)
{
    int bh = blockIdx.x >> 7;
    int i  = blockIdx.x & 127;
    float* row = s + ((size_t)bh * MEMN + i) * TOTAL;
    int tid = threadIdx.x;
    int limit = MEMN + i;           // valid keys j <= limit
    bool valid = (tid <= limit);
    float v = valid ? row[tid] : -3.4e38f;
    float m = block_max256(v);
    float e = valid ? expf(v - m) : 0.f;
    float sum = block_sum256(e);
    row[tid] = e / sum;
}

// ---------------- O = P@V, written straight into y chunk --------------------
// grid (it=2, bh=64), block 256: 64x128 output tile, 4x8 per thread
__global__ void __launch_bounds__(256) pv_kernel(
    const float* __restrict__ p, const float* __restrict__ v,
    float* __restrict__ y, int chunk)
{
    __shared__ float Ps[32][64];    // [j][i]
    __shared__ float Vs[32][128];   // [j][d]
    int bh = blockIdx.y;
    int i0 = blockIdx.x * 64;
    int b = bh >> 4, h = bh & 15;
    int tid = threadIdx.x, tx = tid & 15, ty = tid >> 4;
    const float* pb = p + (size_t)bh * MEMN * TOTAL;
    const float* vb = v + (size_t)bh * TOTAL * HD;
    float acc[4][8] = {};

    for (int j0 = 0; j0 < TOTAL; j0 += 32) {
        for (int t = tid; t < 64 * 8; t += 256) {
            int r = t >> 3;
            int c4 = (t & 7) * 4;
            float4 a = *(const float4*)&pb[(size_t)(i0 + r) * TOTAL + j0 + c4];
            Ps[c4 + 0][r] = a.x; Ps[c4 + 1][r] = a.y;
            Ps[c4 + 2][r] = a.z; Ps[c4 + 3][r] = a.w;
        }
        for (int t = tid; t < 32 * 32; t += 256) {
            int r = t >> 5;
            int c4 = (t & 31) * 4;
            *(float4*)&Vs[r][c4] = *(const float4*)&vb[(size_t)(j0 + r) * HD + c4];
        }
        __syncthreads();
        #pragma unroll
        for (int j = 0; j < 32; j++) {
            float4 a = *(const float4*)&Ps[j][ty * 4];
            float ar[4] = {a.x, a.y, a.z, a.w};
            float4 b0 = *(const float4*)&Vs[j][tx * 8];
            float4 b1 = *(const float4*)&Vs[j][tx * 8 + 4];
            float br[8] = {b0.x, b0.y, b0.z, b0.w, b1.x, b1.y, b1.z, b1.w};
            #pragma unroll
            for (int i = 0; i < 4; i++)
                #pragma unroll
                for (int jc = 0; jc < 8; jc++)
                    acc[i][jc] += ar[i] * br[jc];
        }
        __syncthreads();
    }
    #pragma unroll
    for (int i = 0; i < 4; i++) {
        size_t row = (size_t)b * SEQN + (size_t)chunk * MEMN + i0 + ty * 4 + i;
        float4 o0 = make_float4(acc[i][0], acc[i][1], acc[i][2], acc[i][3]);
        float4 o1 = make_float4(acc[i][4], acc[i][5], acc[i][6], acc[i][7]);
        *(float4*)&y[row * DIMN + h * HD + tx * 8]     = o0;
        *(float4*)&y[row * DIMN + h * HD + tx * 8 + 4] = o1;
    }
}

// ---------------- host orchestration ----------------------------------------
static void launch_gemm(const float* A, const unsigned* Bp, float* C,
                        int M, int N, int K)
{
    dim3 grid(N / GBN, M / GBM);
    gemm_tf32x3_pw<<<grid, 256, GEMM_SMEM>>>(A, Bp, C, M, N, K);
}

static void launch_presplit(unsigned* dst, const float* src, int K, int N)
{
    int total4 = (K * N) / 4;
    presplit_kernel<<<(total4 + 255) / 256, 256>>>(dst, src, K, N);
}

extern "C" void kernel_launch(void* const* d_in, const int* in_sizes, int n_in,
                              void* d_out, int out_size)
{
    (void)in_sizes; (void)n_in; (void)out_size;
    const float* x   = (const float*)d_in[0];
    const float* fc  = (const float*)d_in[1];
    const float* fs  = (const float*)d_in[2];
    const float* om0 = (const float*)d_in[3];
    const float* wq  = (const float*)d_in[4];
    const float* wk  = (const float*)d_in[5];
    const float* wv  = (const float*)d_in[6];
    const float* wo  = (const float*)d_in[7];
    /* d_in[8] = wqm: unused (mq = mk and mq rows are never queried) */
    const float* wkm = (const float*)d_in[9];
    const float* wvm = (const float*)d_in[10];
    const float* wm  = (const float*)d_in[11];
    const float* ffw = (const float*)d_in[12];
    const float* w1  = (const float*)d_in[13];
    const float* w2  = (const float*)d_in[14];
    const float* w3  = (const float*)d_in[15];
    const float* mnw = (const float*)d_in[16];
    float* out = (float*)d_out;

    // raise dynamic smem cap for the GEMM (config call, not a stream op)
    static int smem_configured = 0;
    if (!smem_configured) {
        cudaFuncSetAttribute(gemm_tf32x3_pw,
                             cudaFuncAttributeMaxDynamicSharedMemorySize,
                             GEMM_SMEM);
        smem_configured = 1;
    }

    float *om, *sx, *om2, *h, *g1, *g3, *om4, *mk, *mv, *xq, *xk, *xv;
    float *q, *k, *v, *s, *y;
    cudaGetSymbolAddress((void**)&om,  g_om);
    cudaGetSymbolAddress((void**)&sx,  g_sx);
    cudaGetSymbolAddress((void**)&om2, g_om2);
    cudaGetSymbolAddress((void**)&h,   g_h);
    cudaGetSymbolAddress((void**)&g1,  g_g1);
    cudaGetSymbolAddress((void**)&g3,  g_g3);
    cudaGetSymbolAddress((void**)&om4, g_om4);
    cudaGetSymbolAddress((void**)&mk,  g_mk);
    cudaGetSymbolAddress((void**)&mv,  g_mv);
    cudaGetSymbolAddress((void**)&xq,  g_xq);
    cudaGetSymbolAddress((void**)&xk,  g_xk);
    cudaGetSymbolAddress((void**)&xv,  g_xv);
    cudaGetSymbolAddress((void**)&q,   g_q);
    cudaGetSymbolAddress((void**)&k,   g_k);
    cudaGetSymbolAddress((void**)&v,   g_v);
    cudaGetSymbolAddress((void**)&s,   g_s);
    cudaGetSymbolAddress((void**)&y,   g_y);

    unsigned *pwq, *pwk, *pwv, *pwo, *pwkm, *pwvm, *pwm, *pw1, *pw2, *pw3;
    cudaGetSymbolAddress((void**)&pwq,  g_p_wq);
    cudaGetSymbolAddress((void**)&pwk,  g_p_wk);
    cudaGetSymbolAddress((void**)&pwv,  g_p_wv);
    cudaGetSymbolAddress((void**)&pwo,  g_p_wo);
    cudaGetSymbolAddress((void**)&pwkm, g_p_wkm);
    cudaGetSymbolAddress((void**)&pwvm, g_p_wvm);
    cudaGetSymbolAddress((void**)&pwm,  g_p_wm);
    cudaGetSymbolAddress((void**)&pw1,  g_p_w1);
    cudaGetSymbolAddress((void**)&pw2,  g_p_w2);
    cudaGetSymbolAddress((void**)&pw3,  g_p_w3);

    // pre-split + pre-swizzle all weights once per launch
    launch_presplit(pwq,  wq,  DIMN, DIMN);
    launch_presplit(pwk,  wk,  DIMN, DIMN);
    launch_presplit(pwv,  wv,  DIMN, DIMN);
    launch_presplit(pwo,  wo,  DIMN, DIMN);
    launch_presplit(pwkm, wkm, DIMN, DIMN);
    launch_presplit(pwvm, wvm, DIMN, DIMN);
    launch_presplit(pwm,  wm,  DIMN, DIMN);
    launch_presplit(pw1,  w1,  DIMN, HID);
    launch_presplit(pw3,  w3,  DIMN, HID);
    launch_presplit(pw2,  w2,  HID,  DIMN);

    const float scale = 0.08838834764831845f;   // 1/sqrt(128)

    for (int c = 0; c < NCHUNK; c++) {
        const float* omp;
        if (c == 0) {
            omp = om0;                           // origin_mem is contiguous [512][DIM]
        } else {
            gather_rows<<<RROWS, 256>>>(om, y, c - 1);
            omp = om;
        }
        gather_rows<<<RROWS, 256>>>(sx, x, c);

        // memory-stream FFN block
        launch_gemm(omp, pwm, om2, RROWS, DIMN, DIMN);
        rmsnorm_kernel<<<RROWS, 256>>>(h, om2, ffw);
        launch_gemm(h, pw1, g1, RROWS, HID, DIMN);
        launch_gemm(h, pw3, g3, RROWS, HID, DIMN);
        silu_mul_kernel<<<(RROWS * HID / 4 + 255) / 256, 256>>>(g1, g3);
        launch_gemm(g1, pw2, h, RROWS, DIMN, HID);         // f -> h (h dead now)
        add_rmsnorm_kernel<<<RROWS, 256>>>(om4, om2, h, mnw);

        // projections
        launch_gemm(om4, pwkm, mk, RROWS, DIMN, DIMN);
        launch_gemm(om4, pwvm, mv, RROWS, DIMN, DIMN);
        launch_gemm(sx,  pwq,  xq, RROWS, DIMN, DIMN);
        launch_gemm(sx,  pwk,  xk, RROWS, DIMN, DIMN);
        launch_gemm(sx,  pwv,  xv, RROWS, DIMN, DIMN);

        // assemble roped q/k/v
        build_kv_kernel<<<(BATCH * TOTAL * NH * 64 + 255) / 256, 256>>>(
            mk, mv, xk, xv, fc, fs, k, v);
        build_q_kernel<<<(BATCH * MEMN * NH * 64 + 255) / 256, 256>>>(xq, fc, fs, q);

        // attention (only output rows MEM..2*MEM-1 are needed)
        {
            dim3 g(4, 2, BATCH * NH);
            qk_kernel<<<g, 256>>>(q, k, s, scale);
        }
        softmax_kernel<<<BATCH * NH * MEMN, 256>>>(s);
        {
            dim3 g(2, BATCH * NH);
            pv_kernel<<<g, 256>>>(s, v, y, c);
        }
    }

    // final projection: out = y @ wo
    launch_gemm(y, pwo, out, BATCH * SEQN, DIMN, DIMN);
}

// round 12
// speedup vs baseline: 1.3497x; 1.1096x over previous
#include <cuda_runtime.h>
#include <math.h>

#define DIMN 2048
#define NH 16
#define HD 128
#define MEMN 128
#define SEQN 2048
#define BATCH 4
#define HID 5632
#define NCHUNK (SEQN / MEMN)     // 16
#define RROWS (BATCH * MEMN)     // 512 rows per step
#define TOTAL (2 * MEMN)         // 256
#define EPS 1e-5f

// ---------------- scratch (__device__ globals; no allocation) ----------------
__device__ float g_om  [RROWS * DIMN];
__device__ float g_sx  [RROWS * DIMN];
__device__ float g_om2 [RROWS * DIMN];
__device__ float g_h   [RROWS * DIMN];        // rmsnorm out / FFN out
__device__ float g_g13 [RROWS * 2 * HID];     // fused w1|w3 output
__device__ float g_om4 [RROWS * DIMN];
__device__ float g_mkv [RROWS * 2 * DIMN];    // fused mk|mv
__device__ float g_xqkv[RROWS * 3 * DIMN];    // fused xq|xk|xv
__device__ float g_q  [BATCH * NH * MEMN  * HD];
__device__ float g_k  [BATCH * NH * TOTAL * HD];
__device__ float g_v  [BATCH * NH * TOTAL * HD];
__device__ float g_s  [BATCH * NH * MEMN * TOTAL];
__device__ float g_y  [BATCH * SEQN * DIMN];

// pre-split + pre-swizzled weights (hi/lo interleaved, GEMM B-tile layout)
__device__ unsigned g_p_wm  [DIMN * DIMN * 2];
__device__ unsigned g_p_wo  [DIMN * DIMN * 2];
__device__ unsigned g_p_w2  [HID  * DIMN * 2];
__device__ unsigned g_p_qkv [DIMN * 3 * DIMN * 2];   // wq | wk | wv
__device__ unsigned g_p_kvm [DIMN * 2 * DIMN * 2];   // wkm | wvm
__device__ unsigned g_p_w13 [DIMN * 2 * HID  * 2];   // w1 | w3

// ---------------- reductions ----------------
__device__ __forceinline__ float block_sum256(float v) {
    __shared__ float sh[8];
    #pragma unroll
    for (int o = 16; o > 0; o >>= 1) v += __shfl_xor_sync(0xffffffffu, v, o);
    if ((threadIdx.x & 31) == 0) sh[threadIdx.x >> 5] = v;
    __syncthreads();
    float t = 0.f;
    if (threadIdx.x < 32) {
        t = (threadIdx.x < 8) ? sh[threadIdx.x] : 0.f;
        #pragma unroll
        for (int o = 4; o > 0; o >>= 1) t += __shfl_xor_sync(0xffffffffu, t, o);
        if (threadIdx.x == 0) sh[0] = t;
    }
    __syncthreads();
    float r = sh[0];
    __syncthreads();
    return r;
}

__device__ __forceinline__ float block_max256(float v) {
    __shared__ float sh[8];
    #pragma unroll
    for (int o = 16; o > 0; o >>= 1) v = fmaxf(v, __shfl_xor_sync(0xffffffffu, v, o));
    if ((threadIdx.x & 31) == 0) sh[threadIdx.x >> 5] = v;
    __syncthreads();
    float t = -3.4e38f;
    if (threadIdx.x < 32) {
        t = (threadIdx.x < 8) ? sh[threadIdx.x] : -3.4e38f;
        #pragma unroll
        for (int o = 4; o > 0; o >>= 1) t = fmaxf(t, __shfl_xor_sync(0xffffffffu, t, o));
        if (threadIdx.x == 0) sh[0] = t;
    }
    __syncthreads();
    float r = sh[0];
    __syncthreads();
    return r;
}

// ---------------- tf32 helpers ----------------
__device__ __forceinline__ unsigned f2tf32(float f) {
    unsigned u;
    asm("cvt.rna.tf32.f32 %0, %1;" : "=r"(u) : "f"(f));
    return u;
}

__device__ __forceinline__ void split_tf32(float f, unsigned& hi, unsigned& lo) {
    hi = f2tf32(f);
    lo = f2tf32(f - __uint_as_float(hi));
}

__device__ __forceinline__ void mma_tf32(float c[4], const unsigned a[4], const unsigned b[2]) {
    asm volatile(
        "mma.sync.aligned.m16n8k8.row.col.f32.tf32.tf32.f32 "
        "{%0,%1,%2,%3}, {%4,%5,%6,%7}, {%8,%9}, {%0,%1,%2,%3};"
        : "+f"(c[0]), "+f"(c[1]), "+f"(c[2]), "+f"(c[3])
        : "r"(a[0]), "r"(a[1]), "r"(a[2]), "r"(a[3]), "r"(b[0]), "r"(b[1]));
}

// ---------------- weight pre-split into a concatenated-N layout -------------
// Tile (kt, nt) of 32x128 -> dst tile index (kt * ntiles_tot + nt_off + nt),
// each tile laid out [kr][nc][2] with nc = nl ^ ((kr&3)*8) -- the GEMM's
// smem BsHL layout, so each K-iter copy is one contiguous 32KB block.
__global__ void __launch_bounds__(256) presplit_kernel(
    unsigned* __restrict__ dst, const float* __restrict__ src,
    int K, int N, int nt_off, int ntiles_tot)
{
    int idx = blockIdx.x * 256 + threadIdx.x;   // one float4 per thread
    int total = (K * N) >> 2;
    if (idx >= total) return;
    int nrow4 = N >> 2;
    int k  = idx / nrow4;
    int nn = (idx - k * nrow4) << 2;
    float4 v = ((const float4*)src)[idx];
    int kt = k >> 5, kr = k & 31;
    int nt = nn >> 7, nl = nn & 127;
    int nc = nl ^ ((kr & 3) * 8);
    size_t base = (((size_t)kt * ntiles_tot + nt_off + nt) << 13)
                + ((size_t)kr * 128 + nc) * 2;
    unsigned h0, l0, h1, l1, h2, l2, h3, l3;
    split_tf32(v.x, h0, l0);
    split_tf32(v.y, h1, l1);
    split_tf32(v.z, h2, l2);
    split_tf32(v.w, h3, l3);
    *(uint4*)&dst[base]     = make_uint4(h0, l0, h1, l1);
    *(uint4*)&dst[base + 4] = make_uint4(h2, l2, h3, l3);
}

// ---------------- 3xTF32 tensor-core GEMM, pre-split B, 2-stage pipeline ----
// C[M,N] = A[M,K] @ B[K,N]; A fp32 with row stride lda, Bp pre-split.
// Unchanged mainloop from R10 (per-output math bit-identical).
#define GBM 64
#define GBN 128
#define GBK 32
#define A_BUF_WORDS (GBM * GBK * 2)   // 16KB
#define B_BUF_WORDS (GBK * GBN * 2)   // 32KB
#define GEMM_SMEM ((2 * A_BUF_WORDS + 2 * B_BUF_WORDS) * 4)   // 98304 B

__global__ void __launch_bounds__(256) gemm_tf32x3_pw(
    const float* __restrict__ A, const unsigned* __restrict__ Bp,
    float* __restrict__ C, int M, int N, int K, int lda)
{
    extern __shared__ unsigned su[];
    typedef unsigned ABuf[GBM][GBK][2];
    typedef unsigned BBuf[GBK][GBN][2];
    ABuf* As = (ABuf*)su;
    BBuf* Bs = (BBuf*)(su + 2 * A_BUF_WORDS);

    const int tid  = threadIdx.x;
    const int lane = tid & 31;
    const int wid  = tid >> 5;
    const int warp_m = wid & 1;
    const int warp_n = wid >> 1;
    const int row0 = blockIdx.y * GBM;
    const int col0 = blockIdx.x * GBN;
    const int ntiles = N >> 7;

    unsigned sbB[2];
    sbB[0] = (unsigned)__cvta_generic_to_shared(&Bs[0][0][0][0]);
    sbB[1] = (unsigned)__cvta_generic_to_shared(&Bs[1][0][0][0]);

    float4 ra[2];

    float acc[2][4][4];
    #pragma unroll
    for (int i = 0; i < 2; i++)
        #pragma unroll
        for (int j = 0; j < 4; j++)
            #pragma unroll
            for (int l = 0; l < 4; l++) acc[i][j][l] = 0.f;

    // ---- prologue: stage 0 ----
    {
        const unsigned* btile = Bp + (((size_t)0 * ntiles + (col0 >> 7)) << 13);
        #pragma unroll
        for (int i = 0; i < 8; i++) {
            unsigned d = sbB[0] + (unsigned)(tid + i * 256) * 16u;
            const unsigned* g = btile + (size_t)(tid + i * 256) * 4;
            asm volatile("cp.async.cg.shared.global [%0], [%1], 16;\n"
                         :: "r"(d), "l"(g));
        }
        asm volatile("cp.async.commit_group;\n");
    }
    #pragma unroll
    for (int i = 0; i < 2; i++) {
        int idx = tid + i * 256;
        int m = idx >> 3, k4 = idx & 7;
        ra[i] = *(const float4*)&A[(size_t)(row0 + m) * lda + k4 * 4];
    }
    #pragma unroll
    for (int i = 0; i < 2; i++) {
        int idx = tid + i * 256;
        int m = idx >> 3, k4 = idx & 7;
        int kc = (k4 * 4) ^ ((m & 7) * 4);
        unsigned h0, l0, h1, l1, h2, l2, h3, l3;
        split_tf32(ra[i].x, h0, l0);
        split_tf32(ra[i].y, h1, l1);
        split_tf32(ra[i].z, h2, l2);
        split_tf32(ra[i].w, h3, l3);
        *(uint4*)&As[0][m][kc][0]     = make_uint4(h0, l0, h1, l1);
        *(uint4*)&As[0][m][kc + 2][0] = make_uint4(h2, l2, h3, l3);
    }
    asm volatile("cp.async.wait_group 0;\n" ::: "memory");
    __syncthreads();

    int buf = 0;
    for (int kk = 0; kk < K; kk += GBK) {
        const int nxt = buf ^ 1;
        const bool more = (kk + GBK < K);

        if (more) {
            const unsigned* btile = Bp
                + (((size_t)((kk + GBK) >> 5) * ntiles + (col0 >> 7)) << 13);
            #pragma unroll
            for (int i = 0; i < 8; i++) {
                unsigned d = sbB[nxt] + (unsigned)(tid + i * 256) * 16u;
                const unsigned* g = btile + (size_t)(tid + i * 256) * 4;
                asm volatile("cp.async.cg.shared.global [%0], [%1], 16;\n"
                             :: "r"(d), "l"(g));
            }
            asm volatile("cp.async.commit_group;\n");
            #pragma unroll
            for (int i = 0; i < 2; i++) {
                int idx = tid + i * 256;
                int m = idx >> 3, k4 = idx & 7;
                ra[i] = *(const float4*)&A[(size_t)(row0 + m) * lda + kk + GBK + k4 * 4];
            }
        }

        // ---- compute on buf ----
        #pragma unroll
        for (int ks = 0; ks < 4; ks++) {
            int kq = ks * 8 + (lane & 3);
            int swb = (lane & 3) * 8;
            unsigned afH[2][4], afL[2][4];
            unsigned bfH[4][2], bfL[4][2];
            #pragma unroll
            for (int mf = 0; mf < 2; mf++) {
                int m  = warp_m * 32 + mf * 16 + (lane >> 2);
                int sw = (lane >> 2) * 4;
                uint2 a0 = *(const uint2*)&As[buf][m][kq ^ sw][0];
                uint2 a1 = *(const uint2*)&As[buf][m + 8][kq ^ sw][0];
                uint2 a2 = *(const uint2*)&As[buf][m][(kq + 4) ^ sw][0];
                uint2 a3 = *(const uint2*)&As[buf][m + 8][(kq + 4) ^ sw][0];
                afH[mf][0] = a0.x; afL[mf][0] = a0.y;
                afH[mf][1] = a1.x; afL[mf][1] = a1.y;
                afH[mf][2] = a2.x; afL[mf][2] = a2.y;
                afH[mf][3] = a3.x; afL[mf][3] = a3.y;
            }
            #pragma unroll
            for (int nf = 0; nf < 4; nf++) {
                int n = warp_n * 32 + nf * 8 + (lane >> 2);
                uint2 b0 = *(const uint2*)&Bs[buf][kq][n ^ swb][0];
                uint2 b1 = *(const uint2*)&Bs[buf][kq + 4][n ^ swb][0];
                bfH[nf][0] = b0.x; bfL[nf][0] = b0.y;
                bfH[nf][1] = b1.x; bfL[nf][1] = b1.y;
            }
            #pragma unroll
            for (int mf = 0; mf < 2; mf++)
                #pragma unroll
                for (int nf = 0; nf < 4; nf++) {
                    mma_tf32(acc[mf][nf], afL[mf], bfH[nf]);  // Al*Bh
                    mma_tf32(acc[mf][nf], afH[mf], bfL[nf]);  // Ah*Bl
                    mma_tf32(acc[mf][nf], afH[mf], bfH[nf]);  // Ah*Bh (largest last)
                }
        }

        if (more) {
            #pragma unroll
            for (int i = 0; i < 2; i++) {
                int idx = tid + i * 256;
                int m = idx >> 3, k4 = idx & 7;
                int kc = (k4 * 4) ^ ((m & 7) * 4);
                unsigned h0, l0, h1, l1, h2, l2, h3, l3;
                split_tf32(ra[i].x, h0, l0);
                split_tf32(ra[i].y, h1, l1);
                split_tf32(ra[i].z, h2, l2);
                split_tf32(ra[i].w, h3, l3);
                *(uint4*)&As[nxt][m][kc][0]     = make_uint4(h0, l0, h1, l1);
                *(uint4*)&As[nxt][m][kc + 2][0] = make_uint4(h2, l2, h3, l3);
            }
            asm volatile("cp.async.wait_group 0;\n" ::: "memory");
        }
        __syncthreads();
        buf = nxt;
    }

    // epilogue
    #pragma unroll
    for (int mf = 0; mf < 2; mf++) {
        int row = row0 + warp_m * 32 + mf * 16 + (lane >> 2);
        #pragma unroll
        for (int nf = 0; nf < 4; nf++) {
            int col = col0 + warp_n * 32 + nf * 8 + 2 * (lane & 3);
            *(float2*)&C[(size_t)row * N + col] =
                make_float2(acc[mf][nf][0], acc[mf][nf][1]);
            *(float2*)&C[(size_t)(row + 8) * N + col] =
                make_float2(acc[mf][nf][2], acc[mf][nf][3]);
        }
    }
}

// ---------------- gather rows of a [B][SEQ][DIM] tensor chunk into [512][DIM]
__global__ void __launch_bounds__(256) gather_rows(
    float* __restrict__ dst, const float* __restrict__ src, int chunk)
{
    int row = blockIdx.x;
    int b = row >> 7, i = row & 127;
    const float4* s = (const float4*)&src[((size_t)b * SEQN + chunk * MEMN + i) * DIMN];
    float4* d = (float4*)&dst[(size_t)row * DIMN];
    #pragma unroll
    for (int t = 0; t < 2; t++) d[threadIdx.x + t * 256] = s[threadIdx.x + t * 256];
}

// ---------------- rmsnorm ----------------------------------------------------
__global__ void __launch_bounds__(256) rmsnorm_kernel(
    float* __restrict__ out, const float* __restrict__ in, const float* __restrict__ w)
{
    int row = blockIdx.x;
    const float* xr = in + (size_t)row * DIMN;
    float vals[8];
    float ss = 0.f;
    #pragma unroll
    for (int t = 0; t < 8; t++) {
        float v = xr[threadIdx.x + t * 256];
        vals[t] = v; ss += v * v;
    }
    float tot = block_sum256(ss);
    float sc = rsqrtf(tot * (1.0f / DIMN) + EPS);
    #pragma unroll
    for (int t = 0; t < 8; t++)
        out[(size_t)row * DIMN + threadIdx.x + t * 256] =
            vals[t] * sc * w[threadIdx.x + t * 256];
}

__global__ void __launch_bounds__(256) add_rmsnorm_kernel(
    float* __restrict__ out, const float* __restrict__ a,
    const float* __restrict__ b, const float* __restrict__ w)
{
    int row = blockIdx.x;
    const float* ar = a + (size_t)row * DIMN;
    const float* br = b + (size_t)row * DIMN;
    float vals[8];
    float ss = 0.f;
    #pragma unroll
    for (int t = 0; t < 8; t++) {
        float v = ar[threadIdx.x + t * 256] + br[threadIdx.x + t * 256];
        vals[t] = v; ss += v * v;
    }
    float tot = block_sum256(ss);
    float sc = rsqrtf(tot * (1.0f / DIMN) + EPS);
    #pragma unroll
    for (int t = 0; t < 8; t++)
        out[(size_t)row * DIMN + threadIdx.x + t * 256] =
            vals[t] * sc * w[threadIdx.x + t * 256];
}

// ---------------- fused-buffer silu: g13[:, :HID] = silu(g1) * g3 -----------
__global__ void __launch_bounds__(256) silu_mul_kernel(float* __restrict__ g13)
{
    int idx = blockIdx.x * 256 + threadIdx.x;
    int n4 = RROWS * HID / 4;
    if (idx >= n4) return;
    int row = idx / (HID / 4);
    int c4  = idx - row * (HID / 4);
    float4* ap = (float4*)&g13[(size_t)row * 2 * HID + c4 * 4];
    float4 av = *ap;
    float4 bv = *(const float4*)&g13[(size_t)row * 2 * HID + HID + c4 * 4];
    av.x = av.x / (1.f + expf(-av.x)) * bv.x;
    av.y = av.y / (1.f + expf(-av.y)) * bv.y;
    av.z = av.z / (1.f + expf(-av.z)) * bv.z;
    av.w = av.w / (1.f + expf(-av.w)) * bv.w;
    *ap = av;
}

// ---------------- build K,V from fused buffers with RoPE on K ---------------
__global__ void __launch_bounds__(256) build_kv_kernel(
    const float* __restrict__ mkv, const float* __restrict__ xqkv,
    const float* __restrict__ fc, const float* __restrict__ fs,
    float* __restrict__ k, float* __restrict__ v)
{
    int idx = blockIdx.x * 256 + threadIdx.x;
    if (idx >= BATCH * TOTAL * NH * (HD / 2)) return;
    int j   = idx & 63;
    int h   = (idx >> 6) & 15;
    int pos = (idx >> 10) & 255;
    int b   = idx >> 18;
    int col = h * HD + 2 * j;
    const float *sk, *sv;
    if (pos < MEMN) {
        size_t r = (size_t)(b * MEMN + pos) * (2 * DIMN);
        sk = mkv + r + col;            // mk slice
        sv = mkv + r + DIMN + col;     // mv slice
    } else {
        size_t r = (size_t)(b * MEMN + pos - MEMN) * (3 * DIMN);
        sk = xqkv + r + DIMN + col;    // xk slice
        sv = xqkv + r + 2 * DIMN + col;// xv slice
    }
    float c = fc[pos * 64 + j], s = fs[pos * 64 + j];
    float kr = sk[0], ki = sk[1];
    size_t o = ((size_t)(b * NH + h) * TOTAL + pos) * HD + 2 * j;
    k[o]     = kr * c - ki * s;
    k[o + 1] = kr * s + ki * c;
    v[o]     = sv[0];
    v[o + 1] = sv[1];
}

// ---------------- build Q (xq slice of fused buffer) with RoPE --------------
__global__ void __launch_bounds__(256) build_q_kernel(
    const float* __restrict__ xqkv, const float* __restrict__ fc,
    const float* __restrict__ fs, float* __restrict__ q)
{
    int idx = blockIdx.x * 256 + threadIdx.x;
    if (idx >= BATCH * MEMN * NH * (HD / 2)) return;
    int j = idx & 63;
    int h = (idx >> 6) & 15;
    int i = (idx >> 10) & 127;
    int b = idx >> 17;
    int pos = MEMN + i;
    const float* src = xqkv + (size_t)(b * MEMN + i) * (3 * DIMN) + h * HD + 2 * j;
    float c = fc[pos * 64 + j], s = fs[pos * 64 + j];
    float r = src[0], im = src[1];
    size_t o = ((size_t)(b * NH + h) * MEMN + i) * HD + 2 * j;
    q[o]     = r * c - im * s;
    q[o + 1] = r * s + im * c;
}

// ---------------- S[bh][i][j] = scale * q[bh][i]·k[bh][j] -------------------
__global__ void __launch_bounds__(256) qk_kernel(
    const float* __restrict__ q, const float* __restrict__ k,
    float* __restrict__ s, float scale)
{
    __shared__ float Qs[64][64];
    __shared__ float Ks[64][64];
    int bh = blockIdx.z;
    int i0 = blockIdx.y * 64;
    int j0 = blockIdx.x * 64;
    int tid = threadIdx.x, tx = tid & 15, ty = tid >> 4;
    const float* qb = q + (size_t)bh * MEMN * HD;
    const float* kb = k + (size_t)bh * TOTAL * HD;
    float acc[4][4] = {};

    for (int dc = 0; dc < HD; dc += 64) {
        for (int t = tid; t < 64 * 16; t += 256) {
            int r = t >> 4;
            int c4 = (t & 15) * 4;
            float4 a = *(const float4*)&qb[(size_t)(i0 + r) * HD + dc + c4];
            Qs[c4 + 0][r] = a.x; Qs[c4 + 1][r] = a.y;
            Qs[c4 + 2][r] = a.z; Qs[c4 + 3][r] = a.w;
            float4 b = *(const float4*)&kb[(size_t)(j0 + r) * HD + dc + c4];
            Ks[c4 + 0][r] = b.x; Ks[c4 + 1][r] = b.y;
            Ks[c4 + 2][r] = b.z; Ks[c4 + 3][r] = b.w;
        }
        __syncthreads();
        #pragma unroll
        for (int d = 0; d < 64; d++) {
            float4 a = *(const float4*)&Qs[d][ty * 4];
            float4 b = *(const float4*)&Ks[d][tx * 4];
            float ar[4] = {a.x, a.y, a.z, a.w};
            float br[4] = {b.x, b.y, b.z, b.w};
            #pragma unroll
            for (int i = 0; i < 4; i++)
                #pragma unroll
                for (int j = 0; j < 4; j++)
                    acc[i][j] += ar[i] * br[j];
        }
        __syncthreads();
    }
    #pragma unroll
    for (int i = 0; i < 4; i++) {
        float4 o = make_float4(acc[i][0] * scale, acc[i][1] * scale,
                               acc[i][2] * scale, acc[i][3] * scale);
        *(float4*)&s[((size_t)bh * MEMN + i0 + ty * 4 + i) * TOTAL + j0 + tx * 4] = o;
    }
}

// ---------------- causal softmax ---------------------------------------------
__global__ void __launch_bounds__(256) softmax_kernel(float* __restrict__ s)
{
    int bh = blockIdx.x >> 7;
    int i  = blockIdx.x & 127;
    float* row = s + ((size_t)bh * MEMN + i) * TOTAL;
    int tid = threadIdx.x;
    int limit = MEMN + i;
    bool valid = (tid <= limit);
    float v = valid ? row[tid] : -3.4e38f;
    float m = block_max256(v);
    float e = valid ? expf(v - m) : 0.f;
    float sum = block_sum256(e);
    row[tid] = e / sum;
}

// ---------------- O = P@V -> y chunk -----------------------------------------
__global__ void __launch_bounds__(256) pv_kernel(
    const float* __restrict__ p, const float* __restrict__ v,
    float* __restrict__ y, int chunk)
{
    __shared__ float Ps[32][64];
    __shared__ float Vs[32][128];
    int bh = blockIdx.y;
    int i0 = blockIdx.x * 64;
    int b = bh >> 4, h = bh & 15;
    int tid = threadIdx.x, tx = tid & 15, ty = tid >> 4;
    const float* pb = p + (size_t)bh * MEMN * TOTAL;
    const float* vb = v + (size_t)bh * TOTAL * HD;
    float acc[4][8] = {};

    for (int j0 = 0; j0 < TOTAL; j0 += 32) {
        for (int t = tid; t < 64 * 8; t += 256) {
            int r = t >> 3;
            int c4 = (t & 7) * 4;
            float4 a = *(const float4*)&pb[(size_t)(i0 + r) * TOTAL + j0 + c4];
            Ps[c4 + 0][r] = a.x; Ps[c4 + 1][r] = a.y;
            Ps[c4 + 2][r] = a.z; Ps[c4 + 3][r] = a.w;
        }
        for (int t = tid; t < 32 * 32; t += 256) {
            int r = t >> 5;
            int c4 = (t & 31) * 4;
            *(float4*)&Vs[r][c4] = *(const float4*)&vb[(size_t)(j0 + r) * HD + c4];
        }
        __syncthreads();
        #pragma unroll
        for (int j = 0; j < 32; j++) {
            float4 a = *(const float4*)&Ps[j][ty * 4];
            float ar[4] = {a.x, a.y, a.z, a.w};
            float4 b0 = *(const float4*)&Vs[j][tx * 8];
            float4 b1 = *(const float4*)&Vs[j][tx * 8 + 4];
            float br[8] = {b0.x, b0.y, b0.z, b0.w, b1.x, b1.y, b1.z, b1.w};
            #pragma unroll
            for (int i = 0; i < 4; i++)
                #pragma unroll
                for (int jc = 0; jc < 8; jc++)
                    acc[i][jc] += ar[i] * br[jc];
        }
        __syncthreads();
    }
    #pragma unroll
    for (int i = 0; i < 4; i++) {
        size_t row = (size_t)b * SEQN + (size_t)chunk * MEMN + i0 + ty * 4 + i;
        float4 o0 = make_float4(acc[i][0], acc[i][1], acc[i][2], acc[i][3]);
        float4 o1 = make_float4(acc[i][4], acc[i][5], acc[i][6], acc[i][7]);
        *(float4*)&y[row * DIMN + h * HD + tx * 8]     = o0;
        *(float4*)&y[row * DIMN + h * HD + tx * 8 + 4] = o1;
    }
}

// ---------------- host orchestration ----------------------------------------
static void launch_gemm(const float* A, const unsigned* Bp, float* C,
                        int M, int N, int K, int lda)
{
    dim3 grid(N / GBN, M / GBM);
    gemm_tf32x3_pw<<<grid, 256, GEMM_SMEM>>>(A, Bp, C, M, N, K, lda);
}

static void launch_presplit(unsigned* dst, const float* src, int K, int N,
                            int nt_off, int ntiles_tot)
{
    int total4 = (K * N) / 4;
    presplit_kernel<<<(total4 + 255) / 256, 256>>>(dst, src, K, N, nt_off, ntiles_tot);
}

extern "C" void kernel_launch(void* const* d_in, const int* in_sizes, int n_in,
                              void* d_out, int out_size)
{
    (void)in_sizes; (void)n_in; (void)out_size;
    const float* x   = (const float*)d_in[0];
    const float* fc  = (const float*)d_in[1];
    const float* fs  = (const float*)d_in[2];
    const float* om0 = (const float*)d_in[3];
    const float* wq  = (const float*)d_in[4];
    const float* wk  = (const float*)d_in[5];
    const float* wv  = (const float*)d_in[6];
    const float* wo  = (const float*)d_in[7];
    /* d_in[8] = wqm: unused (mq = mk and mq rows are never queried) */
    const float* wkm = (const float*)d_in[9];
    const float* wvm = (const float*)d_in[10];
    const float* wm  = (const float*)d_in[11];
    const float* ffw = (const float*)d_in[12];
    const float* w1  = (const float*)d_in[13];
    const float* w2  = (const float*)d_in[14];
    const float* w3  = (const float*)d_in[15];
    const float* mnw = (const float*)d_in[16];
    float* out = (float*)d_out;

    static int smem_configured = 0;
    if (!smem_configured) {
        cudaFuncSetAttribute(gemm_tf32x3_pw,
                             cudaFuncAttributeMaxDynamicSharedMemorySize,
                             GEMM_SMEM);
        smem_configured = 1;
    }

    float *om, *sx, *om2, *h, *g13, *om4, *mkv, *xqkv, *q, *k, *v, *s, *y;
    cudaGetSymbolAddress((void**)&om,   g_om);
    cudaGetSymbolAddress((void**)&sx,   g_sx);
    cudaGetSymbolAddress((void**)&om2,  g_om2);
    cudaGetSymbolAddress((void**)&h,    g_h);
    cudaGetSymbolAddress((void**)&g13,  g_g13);
    cudaGetSymbolAddress((void**)&om4,  g_om4);
    cudaGetSymbolAddress((void**)&mkv,  g_mkv);
    cudaGetSymbolAddress((void**)&xqkv, g_xqkv);
    cudaGetSymbolAddress((void**)&q,    g_q);
    cudaGetSymbolAddress((void**)&k,    g_k);
    cudaGetSymbolAddress((void**)&v,    g_v);
    cudaGetSymbolAddress((void**)&s,    g_s);
    cudaGetSymbolAddress((void**)&y,    g_y);

    unsigned *pwm, *pwo, *pw2, *pqkv, *pkvm, *pw13;
    cudaGetSymbolAddress((void**)&pwm,  g_p_wm);
    cudaGetSymbolAddress((void**)&pwo,  g_p_wo);
    cudaGetSymbolAddress((void**)&pw2,  g_p_w2);
    cudaGetSymbolAddress((void**)&pqkv, g_p_qkv);
    cudaGetSymbolAddress((void**)&pkvm, g_p_kvm);
    cudaGetSymbolAddress((void**)&pw13, g_p_w13);

    // pre-split + pre-swizzle all weights once per launch (concatenated-N)
    launch_presplit(pwm,  wm,  DIMN, DIMN, 0, 16);
    launch_presplit(pwo,  wo,  DIMN, DIMN, 0, 16);
    launch_presplit(pw2,  w2,  HID,  DIMN, 0, 16);
    launch_presplit(pqkv, wq,  DIMN, DIMN, 0,  48);
    launch_presplit(pqkv, wk,  DIMN, DIMN, 16, 48);
    launch_presplit(pqkv, wv,  DIMN, DIMN, 32, 48);
    launch_presplit(pkvm, wkm, DIMN, DIMN, 0,  32);
    launch_presplit(pkvm, wvm, DIMN, DIMN, 16, 32);
    launch_presplit(pw13, w1,  DIMN, HID,  0,  88);
    launch_presplit(pw13, w3,  DIMN, HID,  44, 88);

    const float scale = 0.08838834764831845f;   // 1/sqrt(128)

    for (int c = 0; c < NCHUNK; c++) {
        const float* omp;
        if (c == 0) {
            omp = om0;
        } else {
            gather_rows<<<RROWS, 256>>>(om, y, c - 1);
            omp = om;
        }
        gather_rows<<<RROWS, 256>>>(sx, x, c);

        // memory-stream FFN block
        launch_gemm(omp, pwm, om2, RROWS, DIMN, DIMN, DIMN);
        rmsnorm_kernel<<<RROWS, 256>>>(h, om2, ffw);
        launch_gemm(h, pw13, g13, RROWS, 2 * HID, DIMN, DIMN);     // w1|w3 fused
        silu_mul_kernel<<<(RROWS * HID / 4 + 255) / 256, 256>>>(g13);
        launch_gemm(g13, pw2, h, RROWS, DIMN, HID, 2 * HID);       // A = g1 half
        add_rmsnorm_kernel<<<RROWS, 256>>>(om4, om2, h, mnw);

        // fused projections
        launch_gemm(om4, pkvm, mkv,  RROWS, 2 * DIMN, DIMN, DIMN); // wkm|wvm
        launch_gemm(sx,  pqkv, xqkv, RROWS, 3 * DIMN, DIMN, DIMN); // wq|wk|wv

        // assemble roped q/k/v
        build_kv_kernel<<<(BATCH * TOTAL * NH * 64 + 255) / 256, 256>>>(
            mkv, xqkv, fc, fs, k, v);
        build_q_kernel<<<(BATCH * MEMN * NH * 64 + 255) / 256, 256>>>(xqkv, fc, fs, q);

        // attention (only output rows MEM..2*MEM-1 are needed)
        {
            dim3 g(4, 2, BATCH * NH);
            qk_kernel<<<g, 256>>>(q, k, s, scale);
        }
        softmax_kernel<<<BATCH * NH * MEMN, 256>>>(s);
        {
            dim3 g(2, BATCH * NH);
            pv_kernel<<<g, 256>>>(s, v, y, c);
        }
    }

    // final projection: out = y @ wo
    launch_gemm(y, pwo, out, BATCH * SEQN, DIMN, DIMN, DIMN);
}